// round 12
// baseline (speedup 1.0000x reference)
#include <cuda_runtime.h>
#include <cuda_bf16.h>
#include <cstdint>

#define BB 32
#define CC 384
#define TT 512
#define MAX_FRAMES 6656   // TT * 13
#define G 8               // channels per expand block
#define CGROUPS (CC / G)  // 48
#define NT 512            // threads per block

// out layout in d_out (float):
//   [0, BB*CC*MAX_FRAMES)            : out (b, c, pos)
//   [+0, +BB*MAX_FRAMES)             : pitch (b, pos)
//   [+0, +BB)                        : frame_lengths (as float value)
#define OUT_ELEMS   ((size_t)BB * CC * MAX_FRAMES)
#define PITCH_OFF   OUT_ELEMS
#define LEN_OFF     (OUT_ELEMS + (size_t)BB * MAX_FRAMES)

// ---------------------------------------------------------------------------
// Single fused kernel. grid = (CGROUPS+1, BB), 512 threads.
//   cg <  CGROUPS : expand G=8 channels of x
//   cg == CGROUPS : write pitch + frame_lengths
// Each block recomputes repeat counts + shfl scan, then writes the tok map
// exactly once per position: scatter over [0,L), 511-fill over [L,MAX).
// Output stores use streaming (.cs) hints — output is never re-read.
// ---------------------------------------------------------------------------
__global__ void __launch_bounds__(NT) fused_kernel(
    const float* __restrict__ x,
    const float* __restrict__ notepitch,
    const float* __restrict__ duration,
    float* __restrict__ out)
{
    const int cg  = blockIdx.x;
    const int b   = blockIdx.y;
    const int tid = threadIdx.x;
    const int lane = tid & 31, wid = tid >> 5;

    __shared__ float xs[G * TT];                     // 16 KB (x rows OR pitch row)
    __shared__ unsigned short tok_s[MAX_FRAMES];     // 13 KB
    __shared__ int wsum[16];
    __shared__ int L_s;

    // ---- repeat count for element tid (exact fp32) ----
    const float d = duration[b * TT + tid];
    int r;
    {
        const float fm = __fsub_rn(__fmul_rn(44100.0f, d), 1024.0f);
        float rr;
        if (fm > 0.0f) rr = fmaxf(__fmul_rn(fm, (1.0f / 256.0f)), 1.0f);
        else           rr = (d == 0.0f) ? 0.0f : 1.0f;
        r = (int)rr;   // truncation toward zero (rr >= 0)
    }

    // ---- load xs: x rows (expand blocks) or notepitch row (pitch block) ----
    if (cg < CGROUPS) {
        const float4* xsrc = (const float4*)(x + ((size_t)b * CC + (size_t)cg * G) * TT);
        float4* xdst = (float4*)xs;
        #pragma unroll
        for (int i = tid; i < G * TT / 4; i += NT) xdst[i] = xsrc[i];
    } else {
        if (tid < TT / 4) {
            ((float4*)xs)[tid] = ((const float4*)(notepitch + b * TT))[tid];
        }
    }

    // ---- inclusive scan of r over 512 threads (shfl + warp sums) ----
    int v = r;
    #pragma unroll
    for (int o = 1; o < 32; o <<= 1) {
        int n = __shfl_up_sync(0xFFFFFFFFu, v, o);
        if (lane >= o) v += n;
    }
    if (lane == 31) wsum[wid] = v;
    __syncthreads();
    if (wid == 0) {
        int s = (lane < 16) ? wsum[lane] : 0;
        #pragma unroll
        for (int o = 1; o < 16; o <<= 1) {
            int n = __shfl_up_sync(0xFFFFFFFFu, s, o);
            if (lane >= o) s += n;
        }
        if (lane < 16) wsum[lane] = s;
    }
    __syncthreads();
    const int base  = (wid > 0) ? wsum[wid - 1] : 0;
    const int incl  = base + v;          // inclusive cumsum at element tid
    const int start = incl - r;          // exclusive prefix
    if (tid == NT - 1) L_s = incl;
    __syncthreads();

    const int L = L_s;

    // ---- tok map: scatter [0,L), 511-fill [L,MAX_FRAMES) — one write/pos ----
    for (int p = start; p < incl; p++)
        tok_s[p] = (unsigned short)tid;
    for (int p = L + tid; p < MAX_FRAMES; p += NT)
        tok_s[p] = 511;
    __syncthreads();

    if (cg == CGROUPS) {
        // ---- pitch + frame_lengths ----
        if (tid == 0) out[LEN_OFF + b] = (float)L;
        float4* pout = (float4*)(out + PITCH_OFF + (size_t)b * MAX_FRAMES);
        for (int i = tid; i < MAX_FRAMES / 4; i += NT) {
            const int pos = i << 2;
            const uint2 tw = ((const uint2*)tok_s)[i];
            const int t0 = tw.x & 0xFFFF, t1 = tw.x >> 16;
            const int t2 = tw.y & 0xFFFF, t3 = tw.y >> 16;
            float4 v4;
            v4.x = (pos + 0 < L) ? (float)(int)xs[t0] : 0.0f;
            v4.y = (pos + 1 < L) ? (float)(int)xs[t1] : 0.0f;
            v4.z = (pos + 2 < L) ? (float)(int)xs[t2] : 0.0f;
            v4.w = (pos + 3 < L) ? (float)(int)xs[t3] : 0.0f;
            __stcs(pout + i, v4);
        }
        return;
    }

    // ---- expand: G channels, float4 streaming stores ----
    float* outbase = out + ((size_t)b * CC + (size_t)cg * G) * MAX_FRAMES;

    for (int i = tid; i < MAX_FRAMES / 4; i += NT) {   // 1664 float4 slots
        const int pos = i << 2;
        const uint2 tw = ((const uint2*)tok_s)[i];
        const int t0 = tw.x & 0xFFFF, t1 = tw.x >> 16;
        const int t2 = tw.y & 0xFFFF, t3 = tw.y >> 16;

        if (pos + 3 < L) {
            #pragma unroll
            for (int c = 0; c < G; c++) {
                const float* xc = xs + c * TT;
                float4 v4 = make_float4(xc[t0], xc[t1], xc[t2], xc[t3]);
                __stcs((float4*)(outbase + (size_t)c * MAX_FRAMES) + i, v4);
            }
        } else if (pos >= L) {
            const float4 z = make_float4(0.0f, 0.0f, 0.0f, 0.0f);
            #pragma unroll
            for (int c = 0; c < G; c++)
                __stcs((float4*)(outbase + (size_t)c * MAX_FRAMES) + i, z);
        } else {
            #pragma unroll
            for (int c = 0; c < G; c++) {
                const float* xc = xs + c * TT;
                float4 v4;
                v4.x = (pos + 0 < L) ? xc[t0] : 0.0f;
                v4.y = (pos + 1 < L) ? xc[t1] : 0.0f;
                v4.z = (pos + 2 < L) ? xc[t2] : 0.0f;
                v4.w = (pos + 3 < L) ? xc[t3] : 0.0f;
                __stcs((float4*)(outbase + (size_t)c * MAX_FRAMES) + i, v4);
            }
        }
    }
}

extern "C" void kernel_launch(void* const* d_in, const int* in_sizes, int n_in,
                              void* d_out, int out_size)
{
    const float* x         = (const float*)d_in[0];
    const float* notepitch = (const float*)d_in[1];
    const float* duration  = (const float*)d_in[2];
    // d_in[3] = x_lengths (unused by the reference)
    float* out = (float*)d_out;

    fused_kernel<<<dim3(CGROUPS + 1, BB), NT>>>(x, notepitch, duration, out);
}